// round 17
// baseline (speedup 1.0000x reference)
#include <cuda_runtime.h>
#include <math.h>
#include <stdint.h>

#define C_DIM   256
#define MED_DIM 128
#define HW_DIM  6400
#define B_DIM   16
#define K_OUT   128
#define P_PIX   16
#define NTHREADS 128
#define XSS     20          // xs row stride in floats (5 float4)

// smem layout in floats (54 KB total -> 4 CTAs/SM)
#define OFF_XS   0          // xs [256][20]                         5120 f
#define OFF_M    5120       // warp-slice pool: 4 x 2048 f          8192 f
                            //   per-warp slice (2048 f):
                            //     stage A: w1 buf0 [0..1024), buf1 [1024..2048)
                            //     stage B: w2 buf0 [0..544), buf1 [544..1088), hb [1152..1792)
                            //   post-B (after barrier): xlt [16][260] @ M[0..4160)
                            //                           prod [128][17] @ M[4160..6336)
#define OFF_SIDX 13312      // sidx: 16 px * 128 ranks = 2048 B = 512 f
#define SMEM_FLOATS 13824
#define SMEM_BYTES (SMEM_FLOATS * 4)

#define HB_OFF   1152       // hb offset within warp slice (rows of 20 floats)
#define XLT_STR  260
#define PROD_OFF 4160

typedef unsigned long long u64;

// Pre-transposed weights (transpose only: NO arithmetic, keeps bits identical)
__device__ float d_w1t[C_DIM * MED_DIM];   // w1t[c][m]  = w1[m][c]
__device__ float d_w2t[MED_DIM * C_DIM];   // w2t[m][c'] = w2[c'][m]
__device__ float d_b1[MED_DIM];
__device__ float d_b2[C_DIM];

__global__ void prep_kernel(const float* __restrict__ w1, const float* __restrict__ b1,
                            const float* __restrict__ w2, const float* __restrict__ b2) {
    int bidx = blockIdx.x;      // 0..255
    int t = threadIdx.x;        // 0..255
    if (t < MED_DIM)  d_w1t[bidx * MED_DIM + t] = w1[t * C_DIM + bidx];
    if (bidx < MED_DIM) d_w2t[bidx * C_DIM + t] = w2[t * MED_DIM + bidx];
    if (bidx == 0 && t < MED_DIM) d_b1[t] = b1[t];
    if (bidx == 1) d_b2[t] = b2[t];
}

// ---- Bit-exact replica of XLA:CPU vectorized exp (Cephes / sse_mathfun lineage) ----
__device__ __forceinline__ float ref_expf(float v) {
    v = fminf(v, 88.3762626647950f);
    v = fmaxf(v, -88.3762626647949f);
    float fx = floorf(__fmaf_rn(v, 1.44269504088896341f, 0.5f));
    float x  = __fmaf_rn(fx, -0.693359375f, v);
    x = __fmaf_rn(fx, 2.12194440e-4f, x);
    float x2 = __fmul_rn(x, x);
    float y = 1.9875691500E-4f;
    y = __fmaf_rn(y, x, 1.3981999507E-3f);
    y = __fmaf_rn(y, x, 8.3334519073E-3f);
    y = __fmaf_rn(y, x, 4.1665795894E-2f);
    y = __fmaf_rn(y, x, 1.6666665459E-1f);
    y = __fmaf_rn(y, x, 5.0000001201E-1f);
    y = __fmaf_rn(y, x2, x);
    y = __fadd_rn(y, 1.0f);
    int n = (int)fx;
    float s = __int_as_float((n + 127) << 23);
    return __fmul_rn(y, s);
}

__device__ __forceinline__ float sigmoid_xla(float x) {
    float e = ref_expf(-x);
    return __fdiv_rn(1.0f, __fadd_rn(1.0f, e));
}

// ---- packed f32x2 helpers (each lane = independent IEEE-rn fp32 op; bit-exact) ----
__device__ __forceinline__ u64 bcast2(float w) {
    u64 o;
    asm("mov.b64 %0, {%1, %1};" : "=l"(o) : "r"(__float_as_uint(w)));
    return o;
}
__device__ __forceinline__ void fma2(u64& acc, u64 a, u64 b) {
    asm("fma.rn.f32x2 %0, %1, %2, %0;" : "+l"(acc) : "l"(a), "l"(b));
}
__device__ __forceinline__ u64 add2(u64 a, u64 b) {
    u64 o;
    asm("add.rn.f32x2 %0, %1, %2;" : "=l"(o) : "l"(a), "l"(b));
    return o;
}

// ---- cp.async helpers (.cg: L2-resident weights, skip L1) ----
__device__ __forceinline__ void cp16(uint32_t dst, const void* src) {
    asm volatile("cp.async.cg.shared.global [%0], [%1], 16;" :: "r"(dst), "l"(src));
}
__device__ __forceinline__ void cp_commit() {
    asm volatile("cp.async.commit_group;" ::: "memory");
}
__device__ __forceinline__ void cp_wait0() {
    asm volatile("cp.async.wait_group 0;" ::: "memory");
}

// compare-exchange: after call, a holds the element that should come FIRST.
__device__ __forceinline__ void ce(u64& a, u64& b, bool up) {
    u64 x = a, y = b;
    bool g = (x > y) == up;
    a = g ? x : y;
    b = g ? y : x;
}

extern __shared__ float smem[];

__global__ void __launch_bounds__(NTHREADS, 4)
csc_main_kernel(const float* __restrict__ x, float* __restrict__ out) {
    float* xs   = smem + OFF_XS;                 // [256][XSS]
    float* mp   = smem + OFF_M;                  // warp-slice pool / xlt / prod
    float* xl_t = mp;                            // [16][260] post-B
    float* prod = mp + PROD_OFF;                 // [128][17] post-sort
    unsigned char* sidx2 = (unsigned char*)(smem + OFF_SIDX);   // [16][128]

    const uint32_t smem_u = (uint32_t)__cvta_generic_to_shared(smem);
    const uint32_t xs_u = smem_u + OFF_XS * 4;

    const int t    = threadIdx.x;
    const int bid  = blockIdx.x;
    const int bb   = bid / 400;
    const int hw0  = (bid % 400) * P_PIX;

    const int tx   = t & 3;      // pixel group: p = tx*4..+3
    const int ty   = t >> 2;     // 0..31
    const int lane = t & 31;
    const int warp = t >> 5;     // 0..3
    const int typ  = ty & 7;     // within-warp m/c' group

    float* slice = mp + warp * 2048;             // this warp's private pool slice
    const uint32_t slice_u = smem_u + (OFF_M + warp * 2048) * 4;

    // ---- group g0: x tile (cooperative) + this warp's w1 chunk 0 slice ----
    const float* xg = x + ((size_t)bb * C_DIM) * HW_DIM + hw0;
#pragma unroll 2
    for (int i = t; i < C_DIM * 4; i += NTHREADS) {
        int c = i >> 2, seg = i & 3;
        cp16(xs_u + (c * 5 + seg) * 16, xg + (size_t)c * HW_DIM + seg * 4);
    }
    // w1 chunk ch slice for warp w: 32 c-rows x 8 float4 (m in [32w,32w+32))
#pragma unroll
    for (int k = 0; k < 8; ++k) {
        int idx = lane + 32 * k;            // 0..255
        int cc = idx >> 3, f = idx & 7;
        cp16(slice_u + idx * 16, (const float4*)d_w1t + cc * 32 + warp * 8 + f);
    }
    cp_commit();

    // ========== Stage A: h[m][p] = sum_c w1[m][c]*x[c][p]  (c ascending, FMA) ==========
    // 8 chunks x 32 c-rows, warp-private double buffers, per-warp cp groups
    u64 a2[4][2];
#pragma unroll
    for (int i = 0; i < 4; ++i) { a2[i][0] = 0ull; a2[i][1] = 0ull; }

#pragma unroll 1
    for (int ch = 0; ch < 8; ++ch) {
        cp_wait0();                      // this warp's chunk ch (and x tile at ch==0)
        if (ch == 0) __syncthreads();    // barrier #1: all warps' x-tile portions landed
        if (ch < 7) {
            uint32_t dstu = slice_u + (((ch + 1) & 1) ? 1024 : 0) * 4;
#pragma unroll
            for (int k = 0; k < 8; ++k) {
                int idx = lane + 32 * k;
                int cc = idx >> 3, f = idx & 7;
                cp16(dstu + idx * 16,
                     (const float4*)d_w1t + ((ch + 1) * 32 + cc) * 32 + warp * 8 + f);
            }
            cp_commit();
        } else {
            // prefetch this warp's w2 chunk 0 (8 m-rows x 16 f4, padded rows of 17 f4)
#pragma unroll
            for (int k = 0; k < 4; ++k) {
                int idx = lane + 32 * k;            // 0..127
                int mm = idx >> 4, f = idx & 15;
                cp16(slice_u + (mm * 17 + f) * 16,
                     (const float4*)d_w2t + mm * 64 + warp * 16 + f);
            }
            cp_commit();
        }
        const float4* wb = (const float4*)(slice + (ch & 1) * 1024);
#pragma unroll 4
        for (int cc = 0; cc < 32; ++cc) {
            float4 wv = wb[cc * 8 + typ];
            ulonglong2 xv = *(const ulonglong2*)&((const float4*)xs)[(ch * 32 + cc) * 5 + tx];
            u64 wp[4] = {bcast2(wv.x), bcast2(wv.y), bcast2(wv.z), bcast2(wv.w)};
#pragma unroll
            for (int i = 0; i < 4; ++i) {
                fma2(a2[i][0], wp[i], xv.x);
                fma2(a2[i][1], wp[i], xv.y);
            }
        }
    }
    // epilogue A: hb slice (rows padded to 20 floats), own-warp region [HB_OFF..HB_OFF+640)
#pragma unroll
    for (int i = 0; i < 4; ++i) {
        int m = ty * 4 + i;                 // in [32*warp, 32*warp+32)
        u64 bp = bcast2(d_b1[m]);
        ulonglong2 hv;
        hv.x = add2(a2[i][0], bp);
        hv.y = add2(a2[i][1], bp);
        *(ulonglong2*)(slice + HB_OFF + (m & 31) * 20 + tx * 4) = hv;
    }
    __syncthreads();   // barrier #2: all hb slices written (w2c0 already in flight)

    // ========== Stage B: x_[c'][p] = sum_m w2[c'][m]*h[m][p]  (m ascending, FMA) ==========
    // 16 chunks x 8 m-rows, warp-private double buffers (rows padded to 17 f4)
    u64 b2[8][2];
#pragma unroll
    for (int i = 0; i < 8; ++i) { b2[i][0] = 0ull; b2[i][1] = 0ull; }

#pragma unroll 1
    for (int ch = 0; ch < 16; ++ch) {
        cp_wait0();                      // this warp's w2 chunk ch
        if (ch < 15) {
            uint32_t dstu = slice_u + (((ch + 1) & 1) ? 544 : 0) * 4;
#pragma unroll
            for (int k = 0; k < 4; ++k) {
                int idx = lane + 32 * k;
                int mm = idx >> 4, f = idx & 15;
                cp16(dstu + (mm * 17 + f) * 16,
                     (const float4*)d_w2t + ((ch + 1) * 8 + mm) * 64 + warp * 16 + f);
            }
            cp_commit();
        }
        const float4* wbB = (const float4*)(slice + (ch & 1) * 544);
#pragma unroll 4
        for (int mm = 0; mm < 8; ++mm) {
            int m = ch * 8 + mm;
            const float4* hrow = (const float4*)(mp + (m >> 5) * 2048 + HB_OFF + (m & 31) * 20);
            ulonglong2 hv = *(const ulonglong2*)&hrow[tx];
            float4 w0  = wbB[mm * 17 + typ * 2];
            float4 w1v = wbB[mm * 17 + typ * 2 + 1];
            u64 wp[8] = {bcast2(w0.x), bcast2(w0.y), bcast2(w0.z), bcast2(w0.w),
                         bcast2(w1v.x), bcast2(w1v.y), bcast2(w1v.z), bcast2(w1v.w)};
#pragma unroll
            for (int i = 0; i < 8; ++i) {
                fma2(b2[i][0], wp[i], hv.x);
                fma2(b2[i][1], wp[i], hv.y);
            }
        }
    }
    __syncthreads();   // barrier #3: all warps done with w2 buffers & hb -> pool reusable

    // ---- epilogue B: bias, write x_ transposed [p][c] (stride 260) into pool ----
#pragma unroll
    for (int i = 0; i < 8; ++i) {
        int cp = ty * 8 + i;
        u64 bp = bcast2(d_b2[cp]);
        u64 v01 = add2(b2[i][0], bp);
        u64 v23 = add2(b2[i][1], bp);
        xl_t[(tx * 4 + 0) * XLT_STR + cp] = __uint_as_float((unsigned)(v01 & 0xFFFFFFFFull));
        xl_t[(tx * 4 + 1) * XLT_STR + cp] = __uint_as_float((unsigned)(v01 >> 32));
        xl_t[(tx * 4 + 2) * XLT_STR + cp] = __uint_as_float((unsigned)(v23 & 0xFFFFFFFFull));
        xl_t[(tx * 4 + 3) * XLT_STR + cp] = __uint_as_float((unsigned)(v23 >> 32));
    }
    __syncthreads();   // barrier #4: xlt visible

    // ========== register-resident bitonic sort: one warp per pixel (4 px/warp) ==========
    // element e = lane*8 + r ; key = (sigmoid_bits << 8) | (255 ^ c) ; key desc, c asc
#pragma unroll 1
    for (int q = 0; q < 4; ++q) {
        int p = warp * 4 + q;
        const float* row = xl_t + p * XLT_STR + lane * 8;
        float4 v0 = *(const float4*)row;
        float4 v1 = *(const float4*)(row + 4);
        float vv[8] = {v0.x, v0.y, v0.z, v0.w, v1.x, v1.y, v1.z, v1.w};
        u64 P[8];
#pragma unroll
        for (int r = 0; r < 8; ++r) {
            unsigned int kb = __float_as_uint(sigmoid_xla(vv[r]));
            P[r] = ((u64)kb << 8) | (u64)(0xFF ^ (lane * 8 + r));
        }

        // k = 2: up = ((r&2)==0), compile-time
        ce(P[0], P[1], true);  ce(P[2], P[3], false);
        ce(P[4], P[5], true);  ce(P[6], P[7], false);
        // k = 4: up = ((r&4)==0), compile-time
        ce(P[0], P[2], true);  ce(P[1], P[3], true);
        ce(P[4], P[6], false); ce(P[5], P[7], false);
        ce(P[0], P[1], true);  ce(P[2], P[3], true);
        ce(P[4], P[5], false); ce(P[6], P[7], false);

        // k = 8..256: shfl levels (j>=8) + uniform-up local levels
#pragma unroll 1
        for (int k = 8; k <= 256; k <<= 1) {
#pragma unroll 1
            for (int j = k >> 1; j >= 8; j >>= 1) {
                int m = j >> 3;
                bool km = ((lane & (k >> 3)) == 0) == ((lane & m) == 0);
#pragma unroll
                for (int r = 0; r < 8; ++r) {
                    u64 qv = __shfl_xor_sync(0xFFFFFFFFu, P[r], m);
                    P[r] = ((P[r] > qv) == km) ? P[r] : qv;
                }
            }
            bool upL = (((lane << 3) & k) == 0);
            ce(P[0], P[4], upL); ce(P[1], P[5], upL);
            ce(P[2], P[6], upL); ce(P[3], P[7], upL);
            ce(P[0], P[2], upL); ce(P[1], P[3], upL);
            ce(P[4], P[6], upL); ce(P[5], P[7], upL);
            ce(P[0], P[1], upL); ce(P[2], P[3], upL);
            ce(P[4], P[5], upL); ce(P[6], P[7], upL);
        }

        // element e holds rank e; only ranks 0..127 needed (lanes 0..15)
        if (lane < 16) {
            u64 wbits = 0;
#pragma unroll
            for (int r = 0; r < 8; ++r)
                wbits |= (u64)(0xFFu ^ (unsigned)(P[r] & 0xFFu)) << (8 * r);
            *(u64*)(sidx2 + p * 128 + lane * 8) = wbits;
        }
    }
    __syncthreads();   // barrier #5: sidx visible

    // ---- gather (rank-major lanes): prod[r][p] = x[c]*x_[c] ; stride-17 staging ----
#pragma unroll 4
    for (int it = 0; it < 16; ++it) {
        int task = t + NTHREADS * it;      // 16 px * 128 ranks
        int r = task & 127;
        int p = task >> 7;
        int c = sidx2[p * 128 + r];
        prod[r * 17 + p] = __fmul_rn(xs[c * XSS + p], xl_t[p * XLT_STR + c]);
    }
    __syncthreads();   // barrier #6: prod visible

    // ---- write (pixel-major lanes): coalesced 64B segments ----
#pragma unroll 4
    for (int it = 0; it < 16; ++it) {
        int task = t + NTHREADS * it;
        int p = task & 15;
        int rr = task >> 4;
        out[((size_t)(bb * K_OUT + rr)) * HW_DIM + hw0 + p] = prod[rr * 17 + p];
    }
}

extern "C" void kernel_launch(void* const* d_in, const int* in_sizes, int n_in,
                              void* d_out, int out_size) {
    const float* x  = (const float*)d_in[0];
    const float* w1 = (const float*)d_in[1];
    const float* b1 = (const float*)d_in[2];
    const float* w2 = (const float*)d_in[3];
    const float* b2 = (const float*)d_in[4];
    float* out = (float*)d_out;

    cudaFuncSetAttribute(csc_main_kernel,
                         cudaFuncAttributeMaxDynamicSharedMemorySize, SMEM_BYTES);
    prep_kernel<<<C_DIM, 256>>>(w1, b1, w2, b2);
    csc_main_kernel<<<(B_DIM * HW_DIM) / P_PIX, NTHREADS, SMEM_BYTES>>>(x, out);
}